// round 10
// baseline (speedup 1.0000x reference)
#include <cuda_runtime.h>
#include <cuda_fp16.h>
#include <math.h>
#include <stdint.h>

// Problem constants
#define NN 8192
#define FF 256
#define DD 128
#define CC 512          // NH*DD feature columns (GEMM N = 512)

// aggr GEMM: CTA tile 256x128, 8 consumer warps (4m x 2n, warp 64x64)
//            + 2 producer warps. XOR-swizzled smem (128B rows).
#define KST 64                    // fp16 K elements per stage
#define NST 4                     // pipeline stages
#define A_BYTES (256 * 128)       // 32768
#define B_BYTES (128 * 128)       // 16384
#define B2_BYTES (16 * 128)       // 2048
#define STAGE (A_BYTES + B_BYTES + B2_BYTES)  // 51200
#define SMEMB (NST * STAGE)       // 204800

// Scratch (device globals; zero-initialized at module load)
__device__ __half g_htT[(size_t)CC * NN];   // 8 MB  lrelu(h@W) transposed [c][j]
__device__ float  g_tgt[4 * NN];
__device__ __half g_wT[16 * NN];            // rows 0..3 = w_h[j]; rows 4..15 zero
__device__ __half g_VT[(size_t)CC * NN];    // 8 MB  V^T = w * htT
__device__ float  g_O[(size_t)NN * CC];     // 16 MB numerators
__device__ float  g_den[NN * 4];            // denominators

// ---------------------------------------------------------------------------
// helpers (sm_80-compatible PTX only)
// ---------------------------------------------------------------------------
__device__ __forceinline__ uint32_t smem_u32(const void* p) {
    uint32_t a;
    asm("{ .reg .u64 t; cvta.to.shared.u64 t, %1; cvt.u32.u64 %0, t; }" : "=r"(a) : "l"(p));
    return a;
}
static __device__ __forceinline__ void cp16(uint32_t dst, const void* src) {
    asm volatile("cp.async.cg.shared.global [%0], [%1], 16;" :: "r"(dst), "l"(src));
}
static __device__ __forceinline__ void cp_commit() {
    asm volatile("cp.async.commit_group;" ::: "memory");
}
__device__ __forceinline__ void ldsm4(uint32_t& r0, uint32_t& r1, uint32_t& r2,
                                      uint32_t& r3, uint32_t addr) {
    asm volatile("ldmatrix.sync.aligned.m8n8.x4.shared.b16 {%0,%1,%2,%3}, [%4];"
                 : "=r"(r0), "=r"(r1), "=r"(r2), "=r"(r3) : "r"(addr));
}
__device__ __forceinline__ void mma16816(float* d, const uint32_t* a,
                                         uint32_t b0, uint32_t b1) {
    asm volatile("mma.sync.aligned.m16n8k16.row.col.f32.f16.f16.f32 "
                 "{%0,%1,%2,%3}, {%4,%5,%6,%7}, {%8,%9}, {%0,%1,%2,%3};"
                 : "+f"(d[0]), "+f"(d[1]), "+f"(d[2]), "+f"(d[3])
                 : "r"(a[0]), "r"(a[1]), "r"(a[2]), "r"(a[3]), "r"(b0), "r"(b1));
}
// swizzled byte offset: row r, 16B chunk c (0..7) within a 128B-row tile
__device__ __forceinline__ uint32_t swz(int r, int c) {
    return (uint32_t)(r * 128 + ((c ^ (r & 7)) << 4));
}

// ---------------------------------------------------------------------------
// Kernel 0: proj HMMA + LeakyReLU + tgt dot + transposed fp16 store
// ---------------------------------------------------------------------------
__global__ __launch_bounds__(256) void k_fused(const float* __restrict__ hp,
                                               const float* __restrict__ W,
                                               const float* __restrict__ av) {
    __shared__ __align__(16) char sm[34816 + 1024];
    const int bid = blockIdx.x;
    const uint32_t sb = smem_u32(sm);
    float* tgtp = reinterpret_cast<float*>(sm + 34816);
    const int tid = threadIdx.x;
    const int lane = tid & 31;
    const int wid = tid >> 5;
    const int wm = wid & 3;
    const int wn = wid >> 2;
    const int m0 = (bid >> 2) * 128;
    const int hh = bid & 3;
    const int n0 = hh * 128;

    float acc[2][8][4];
#pragma unroll
    for (int f = 0; f < 2; f++)
#pragma unroll
        for (int g = 0; g < 8; g++)
#pragma unroll
            for (int e = 0; e < 4; e++) acc[f][g][e] = 0.f;

    const int lr = lane & 15;
    const int lk = (lane >> 4) * 8;

    for (int k0 = 0; k0 < FF; k0 += 32) {
#pragma unroll
        for (int i = 0; i < 4; i++) {
            int idx = i * 256 + tid;
            int r = idx >> 3, c = idx & 7;
            float4 v = *reinterpret_cast<const float4*>(hp + (size_t)(m0 + r) * FF + k0 + c * 4);
            __half2 lo = __floats2half2_rn(v.x, v.y);
            __half2 hi = __floats2half2_rn(v.z, v.w);
            uint2 u = { *reinterpret_cast<uint32_t*>(&lo), *reinterpret_cast<uint32_t*>(&hi) };
            *reinterpret_cast<uint2*>(sm + r * 80 + c * 8) = u;
        }
#pragma unroll
        for (int i = 0; i < 4; i++) {
            int idx = i * 256 + tid;
            int kk = idx >> 5, n4 = idx & 31;
            float4 v = *reinterpret_cast<const float4*>(W + (size_t)(k0 + kk) * CC + n0 + n4 * 4);
            *reinterpret_cast<__half*>(sm + 10240 + (n4 * 4 + 0) * 80 + kk * 2) = __float2half(v.x);
            *reinterpret_cast<__half*>(sm + 10240 + (n4 * 4 + 1) * 80 + kk * 2) = __float2half(v.y);
            *reinterpret_cast<__half*>(sm + 10240 + (n4 * 4 + 2) * 80 + kk * 2) = __float2half(v.z);
            *reinterpret_cast<__half*>(sm + 10240 + (n4 * 4 + 3) * 80 + kk * 2) = __float2half(v.w);
        }
        __syncthreads();
#pragma unroll
        for (int kk = 0; kk < 2; kk++) {
            const uint32_t koff = (kk * 16 + lk) * 2;
            uint32_t af[2][4], bf[4][4];
#pragma unroll
            for (int f = 0; f < 2; f++)
                ldsm4(af[f][0], af[f][1], af[f][2], af[f][3],
                      sb + (wm * 32 + f * 16 + lr) * 80 + koff);
#pragma unroll
            for (int g = 0; g < 4; g++)
                ldsm4(bf[g][0], bf[g][1], bf[g][2], bf[g][3],
                      sb + 10240 + (wn * 64 + g * 16 + lr) * 80 + koff);
#pragma unroll
            for (int f = 0; f < 2; f++)
#pragma unroll
                for (int g = 0; g < 4; g++) {
                    mma16816(acc[f][g * 2 + 0], af[f], bf[g][0], bf[g][2]);
                    mma16816(acc[f][g * 2 + 1], af[f], bf[g][1], bf[g][3]);
                }
        }
        __syncthreads();
    }

#pragma unroll
    for (int f = 0; f < 2; f++)
#pragma unroll
        for (int g = 0; g < 8; g++)
#pragma unroll
            for (int e = 0; e < 4; e++) {
                float x = acc[f][g][e];
                acc[f][g][e] = (x >= 0.f) ? x : 0.1f * x;
            }

    float av0[8], av1[8];
#pragma unroll
    for (int g = 0; g < 8; g++) {
        int col = wn * 64 + g * 8 + (lane & 3) * 2;
        av0[g] = av[hh * 256 + 128 + col];
        av1[g] = av[hh * 256 + 128 + col + 1];
    }
#pragma unroll
    for (int f = 0; f < 2; f++) {
        float s0 = 0.f, s1 = 0.f;
#pragma unroll
        for (int g = 0; g < 8; g++) {
            s0 += acc[f][g][0] * av0[g] + acc[f][g][1] * av1[g];
            s1 += acc[f][g][2] * av0[g] + acc[f][g][3] * av1[g];
        }
        s0 += __shfl_xor_sync(0xFFFFFFFFu, s0, 1);
        s0 += __shfl_xor_sync(0xFFFFFFFFu, s0, 2);
        s1 += __shfl_xor_sync(0xFFFFFFFFu, s1, 1);
        s1 += __shfl_xor_sync(0xFFFFFFFFu, s1, 2);
        if ((lane & 3) == 0) {
            int row = wm * 32 + f * 16 + (lane >> 2);
            tgtp[wn * 128 + row] = s0;
            tgtp[wn * 128 + row + 8] = s1;
        }
    }

#pragma unroll
    for (int f = 0; f < 2; f++) {
        int row = wm * 32 + f * 16 + (lane >> 2);
#pragma unroll
        for (int g = 0; g < 8; g++) {
            int c0 = wn * 64 + g * 8 + (lane & 3) * 2;
            *reinterpret_cast<__half*>(sm + c0 * 272 + row * 2)       = __float2half(acc[f][g][0]);
            *reinterpret_cast<__half*>(sm + (c0 + 1) * 272 + row * 2) = __float2half(acc[f][g][1]);
            *reinterpret_cast<__half*>(sm + c0 * 272 + (row + 8) * 2)       = __float2half(acc[f][g][2]);
            *reinterpret_cast<__half*>(sm + (c0 + 1) * 272 + (row + 8) * 2) = __float2half(acc[f][g][3]);
        }
    }
    __syncthreads();

    if (tid < 128)
        g_tgt[hh * NN + m0 + tid] = tgtp[tid] + tgtp[128 + tid];

#pragma unroll
    for (int i = 0; i < 8; i++) {
        int idx = i * 256 + tid;
        int c = idx >> 4, q = idx & 15;
        *reinterpret_cast<uint4*>(g_htT + (size_t)(hh * 128 + c) * NN + m0 + q * 8) =
            *reinterpret_cast<uint4*>(sm + c * 272 + q * 16);
    }
}

// ---------------------------------------------------------------------------
// Kernel 1: per-head max + w = exp(tgt - max)
// ---------------------------------------------------------------------------
__global__ __launch_bounds__(256) void k_maxw() {
    __shared__ float red[256];
    const int hh = blockIdx.x;
    const int tid = threadIdx.x;
    float m = -1e30f;
    for (int j = tid; j < NN; j += 256) m = fmaxf(m, g_tgt[hh * NN + j]);
    red[tid] = m;
    __syncthreads();
#pragma unroll
    for (int s = 128; s; s >>= 1) {
        if (tid < s) red[tid] = fmaxf(red[tid], red[tid + s]);
        __syncthreads();
    }
    const float mh = red[0];
    for (int j = tid; j < NN; j += 256)
        g_wT[hh * NN + j] = __float2half(expf(g_tgt[hh * NN + j] - mh));
}

// ---------------------------------------------------------------------------
// Kernel 2: VT[n][j] = htT[n][j] * wT[n>>7][j]
// ---------------------------------------------------------------------------
__global__ __launch_bounds__(256) void k_buildVT() {
    size_t idx = ((size_t)blockIdx.x * 256 + threadIdx.x) * 8;
    int n = (int)(idx >> 13);
    int j = (int)(idx & 8191);
    uint4 hv = *reinterpret_cast<const uint4*>(g_htT + idx);
    const __half2* wp = reinterpret_cast<const __half2*>(g_wT + (size_t)(n >> 7) * NN + j);
    __half2* hp2 = reinterpret_cast<__half2*>(&hv);
#pragma unroll
    for (int e = 0; e < 4; e++) hp2[e] = __hmul2(hp2[e], wp[e]);
    *reinterpret_cast<uint4*>(g_VT + idx) = hv;
}

// ---------------------------------------------------------------------------
// Kernel 3: O = A @ V. 320 threads: warps 0-7 consume (r8 mainloop, warp 64x64),
// warps 8-9 produce (int32 adj -> fp16 in-register -> STS; cp.async for B/B2).
// No conversion pre-pass. grid (4 n fast, 32 m) = 128 CTAs. den fused.
// ---------------------------------------------------------------------------
__device__ __forceinline__ void produce_stage(int t, char* smp, uint32_t sb,
                                              const int* __restrict__ Adj,
                                              int m0, int n0, int pid) {
    const int k0 = t * KST;
    char* base = smp + (t & (NST - 1)) * STAGE;
    const uint32_t ub = sb + (t & (NST - 1)) * STAGE;
    // A: 256 rows x 8 chunks (16B fp16 each <- 8 ints) = 2048 -> 32/lane
#pragma unroll 4
    for (int i = 0; i < 32; i++) {
        int idx = i * 64 + pid;
        int r = idx >> 3, c = idx & 7;
        const int4* p = reinterpret_cast<const int4*>(Adj + (size_t)(m0 + r) * NN + k0 + c * 8);
        int4 a = p[0], b = p[1];
        uint4 o;
        o.x = (uint32_t)(a.x | (a.y << 16)) * 0x3C00u;
        o.y = (uint32_t)(a.z | (a.w << 16)) * 0x3C00u;
        o.z = (uint32_t)(b.x | (b.y << 16)) * 0x3C00u;
        o.w = (uint32_t)(b.z | (b.w << 16)) * 0x3C00u;
        *reinterpret_cast<uint4*>(base + swz(r, c)) = o;
    }
    // B: 128 rows x 8 chunks = 1024 -> 16/lane
#pragma unroll
    for (int i = 0; i < 16; i++) {
        int idx = i * 64 + pid;
        int r = idx >> 3, c = idx & 7;
        cp16(ub + A_BYTES + swz(r, c), g_VT + (size_t)(n0 + r) * NN + k0 + c * 8);
    }
    // B2: 16 rows x 8 chunks = 128 -> 2/lane
#pragma unroll
    for (int i = 0; i < 2; i++) {
        int idx = i * 64 + pid;
        int r = idx >> 3, c = idx & 7;
        cp16(ub + A_BYTES + B_BYTES + swz(r, c), g_wT + (size_t)r * NN + k0 + c * 8);
    }
}

__global__ __launch_bounds__(320, 1) void k_aggr_mma(const int* __restrict__ Adj) {
    extern __shared__ __align__(128) char smem[];
    const uint32_t sb = smem_u32(smem);
    const int tid = threadIdx.x;
    const int lane = tid & 31;
    const int wid = tid >> 5;
    const int n0 = blockIdx.x * 128;
    const int m0 = blockIdx.y * 256;
    const int S = NN / KST;  // 128

    if (wid >= 8) {
        // ================= producer warps =================
        const int pid = tid - 256;
#pragma unroll
        for (int p = 0; p < NST - 1; p++) {
            produce_stage(p, smem, sb, Adj, m0, n0, pid);
            cp_commit();
        }
        for (int s = 0; s < S; s++) {
            asm volatile("cp.async.wait_group %0;" :: "n"(NST - 2) : "memory");
            __syncthreads();
            const int t2 = s + NST - 1;
            if (t2 < S) produce_stage(t2, smem, sb, Adj, m0, n0, pid);
            cp_commit();
        }
        return;
    }

    // ================= consumer warps =================
    const int wm = wid & 3;
    const int wn = wid >> 2;
    const bool do_den = (blockIdx.x == 0) && (wn == 0);

    float acc[4][8][4];
#pragma unroll
    for (int f = 0; f < 4; f++)
#pragma unroll
        for (int g = 0; g < 8; g++)
#pragma unroll
            for (int e = 0; e < 4; e++) acc[f][g][e] = 0.f;
    float dacc[4][4];
#pragma unroll
    for (int f = 0; f < 4; f++)
#pragma unroll
        for (int e = 0; e < 4; e++) dacc[f][e] = 0.f;

    const int lr = lane & 15;
    const int lcol = lane >> 4;

    for (int s = 0; s < S; s++) {
        __syncthreads();
        const uint32_t st = sb + (s & (NST - 1)) * STAGE;
#pragma unroll
        for (int kk = 0; kk < 4; kk++) {
            const int c16 = kk * 2 + lcol;
            uint32_t af[4][4], bf[4][4];
#pragma unroll
            for (int f = 0; f < 4; f++) {
                int r = wm * 64 + f * 16 + lr;
                ldsm4(af[f][0], af[f][1], af[f][2], af[f][3], st + swz(r, c16));
            }
#pragma unroll
            for (int g = 0; g < 4; g++) {
                int r = wn * 64 + g * 16 + lr;
                ldsm4(bf[g][0], bf[g][1], bf[g][2], bf[g][3],
                      st + A_BYTES + swz(r, c16));
            }
#pragma unroll
            for (int f = 0; f < 4; f++)
#pragma unroll
                for (int g = 0; g < 4; g++) {
                    mma16816(acc[f][g * 2 + 0], af[f], bf[g][0], bf[g][2]);
                    mma16816(acc[f][g * 2 + 1], af[f], bf[g][1], bf[g][3]);
                }
            if (do_den) {
                uint32_t bw[4];
                ldsm4(bw[0], bw[1], bw[2], bw[3],
                      st + A_BYTES + B_BYTES + swz(lr, c16));
#pragma unroll
                for (int f = 0; f < 4; f++)
                    mma16816(dacc[f], af[f], bw[0], bw[2]);
            }
        }
    }

    // epilogue: numerators
#pragma unroll
    for (int f = 0; f < 4; f++) {
        const int row = m0 + wm * 64 + f * 16 + (lane >> 2);
#pragma unroll
        for (int g = 0; g < 8; g++) {
            const int col = n0 + wn * 64 + g * 8 + (lane & 3) * 2;
            float2 v0 = {acc[f][g][0], acc[f][g][1]};
            float2 v1 = {acc[f][g][2], acc[f][g][3]};
            *reinterpret_cast<float2*>(g_O + (size_t)row * CC + col) = v0;
            *reinterpret_cast<float2*>(g_O + (size_t)(row + 8) * CC + col) = v1;
        }
    }
    if (do_den) {
        const int c2 = (lane & 3) * 2;
        if (c2 < 4) {
#pragma unroll
            for (int f = 0; f < 4; f++) {
                const int row = m0 + wm * 64 + f * 16 + (lane >> 2);
                g_den[row * 4 + c2 + 0] = dacc[f][0];
                g_den[row * 4 + c2 + 1] = dacc[f][1];
                g_den[(row + 8) * 4 + c2 + 0] = dacc[f][2];
                g_den[(row + 8) * 4 + c2 + 1] = dacc[f][3];
            }
        }
    }
}

// ---------------------------------------------------------------------------
// Kernel 4: out[i][d] = 0.25 * sum_h num[h]/den[h]
// ---------------------------------------------------------------------------
__global__ __launch_bounds__(128) void k_out(float* __restrict__ out) {
    const int i = blockIdx.x;
    const int d = threadIdx.x;
    __shared__ float inv[4];
    if (d < 4) inv[d] = 1.0f / g_den[i * 4 + d];
    __syncthreads();
    float s = 0.f;
#pragma unroll
    for (int h = 0; h < 4; h++) s += g_O[(size_t)i * CC + h * DD + d] * inv[h];
    out[(size_t)i * DD + d] = 0.25f * s;
}

// ---------------------------------------------------------------------------
extern "C" void kernel_launch(void* const* d_in, const int* in_sizes, int n_in,
                              void* d_out, int out_size) {
    const float* h   = (const float*)d_in[0];
    const int*   adj = (const int*)d_in[1];
    const float* W   = (const float*)d_in[2];
    const float* a   = (const float*)d_in[3];
    float* out = (float*)d_out;

    static int init_done = 0;
    if (!init_done) {
        cudaFuncSetAttribute(k_aggr_mma, cudaFuncAttributeMaxDynamicSharedMemorySize, SMEMB);
        init_done = 1;
    }

    k_fused<<<256, 256>>>(h, W, a);                 // launch 0: proj (conv deleted)
    k_maxw<<<4, 256>>>();                           // launch 1
    k_buildVT<<<2048, 256>>>();                     // launch 2
    k_aggr_mma<<<dim3(4, 32), 320, SMEMB>>>(adj);   // launch 3  <- profiled
    k_out<<<8192, 128>>>(out);                      // launch 4
}

// round 11
// speedup vs baseline: 2.6947x; 2.6947x over previous
#include <cuda_runtime.h>
#include <cuda_fp16.h>
#include <math.h>
#include <stdint.h>

// Problem constants
#define NN 8192
#define FF 256
#define DD 128
#define CC 512          // NH*DD feature columns (GEMM N = 512)

// aggr GEMM tiling (r8 proven): CTA 256x128, 8 warps (4m x 2n), warp 64x64
// XOR-swizzled smem rows (128B), 16B chunk c' = c ^ (r&7)
#define KST 64                    // fp16 K elements per stage
#define NST 4                     // pipeline stages
#define A_BYTES (256 * 128)       // 32768
#define B_BYTES (128 * 128)       // 16384
#define B2_BYTES (16 * 128)       // 2048
#define STAGE (A_BYTES + B_BYTES + B2_BYTES)  // 51200
#define SMEMB (NST * STAGE)       // 204800
#define KHALF 4096

// Scratch (device globals; zero-initialized at module load)
__device__ __half g_htT[(size_t)CC * NN];   // 8 MB  lrelu(h@W) transposed [c][j]
__device__ float  g_tgt[4 * NN];
__device__ __half g_wT[16 * NN];            // rows 0..3 = w_h[j]; rows 4..15 zero
__device__ __half g_Ah[(size_t)NN * NN];    // 128 MB adjacency as fp16
__device__ __half g_VT[(size_t)CC * NN];    // 8 MB  V^T = w * htT
__device__ float  g_O[(size_t)NN * CC];     // 16 MB numerators
__device__ float  g_den[NN * 4];            // denominators

// ---------------------------------------------------------------------------
// helpers (sm_80-compatible PTX only)
// ---------------------------------------------------------------------------
__device__ __forceinline__ uint32_t smem_u32(const void* p) {
    uint32_t a;
    asm("{ .reg .u64 t; cvta.to.shared.u64 t, %1; cvt.u32.u64 %0, t; }" : "=r"(a) : "l"(p));
    return a;
}
static __device__ __forceinline__ void cp16(uint32_t dst, const void* src) {
    asm volatile("cp.async.cg.shared.global [%0], [%1], 16;" :: "r"(dst), "l"(src));
}
static __device__ __forceinline__ void cp_commit() {
    asm volatile("cp.async.commit_group;" ::: "memory");
}
__device__ __forceinline__ void ldsm4(uint32_t& r0, uint32_t& r1, uint32_t& r2,
                                      uint32_t& r3, uint32_t addr) {
    asm volatile("ldmatrix.sync.aligned.m8n8.x4.shared.b16 {%0,%1,%2,%3}, [%4];"
                 : "=r"(r0), "=r"(r1), "=r"(r2), "=r"(r3) : "r"(addr));
}
__device__ __forceinline__ void mma16816(float* d, const uint32_t* a,
                                         uint32_t b0, uint32_t b1) {
    asm volatile("mma.sync.aligned.m16n8k16.row.col.f32.f16.f16.f32 "
                 "{%0,%1,%2,%3}, {%4,%5,%6,%7}, {%8,%9}, {%0,%1,%2,%3};"
                 : "+f"(d[0]), "+f"(d[1]), "+f"(d[2]), "+f"(d[3])
                 : "r"(a[0]), "r"(a[1]), "r"(a[2]), "r"(a[3]), "r"(b0), "r"(b1));
}
// swizzled byte offset: row r, 16B chunk c (0..7) within a 128B-row tile
__device__ __forceinline__ uint32_t swz(int r, int c) {
    return (uint32_t)(r * 128 + ((c ^ (r & 7)) << 4));
}

// ---------------------------------------------------------------------------
// Kernel conv: int32 adjacency -> fp16, one K-half ([kbase, kbase+4096))
// bit trick: (a|b<<16)*0x3C00 packs {0,1}x{0,1} -> fp16x2 exactly
// ---------------------------------------------------------------------------
__global__ __launch_bounds__(256) void k_conv(const int* __restrict__ A, int kbase) {
    size_t idx = ((size_t)blockIdx.x * 256 + threadIdx.x) * 8;  // index within half
    int r = (int)(idx >> 12);
    int c = (int)(idx & 4095);
    size_t off = (size_t)r * NN + kbase + c;
    int4 a = *reinterpret_cast<const int4*>(A + off);
    int4 b = *reinterpret_cast<const int4*>(A + off + 4);
    uint4 o;
    o.x = (uint32_t)(a.x | (a.y << 16)) * 0x3C00u;
    o.y = (uint32_t)(a.z | (a.w << 16)) * 0x3C00u;
    o.z = (uint32_t)(b.x | (b.y << 16)) * 0x3C00u;
    o.w = (uint32_t)(b.z | (b.w << 16)) * 0x3C00u;
    *reinterpret_cast<uint4*>(g_Ah + off) = o;
}

// ---------------------------------------------------------------------------
// Kernel proj: HMMA fp16 proj + LeakyReLU + tgt dot + transposed fp16 store
// ---------------------------------------------------------------------------
__global__ __launch_bounds__(256) void k_proj(const float* __restrict__ hp,
                                              const float* __restrict__ W,
                                              const float* __restrict__ av) {
    __shared__ __align__(16) char sm[34816 + 1024];
    const int bid = blockIdx.x;
    const uint32_t sb = smem_u32(sm);
    float* tgtp = reinterpret_cast<float*>(sm + 34816);
    const int tid = threadIdx.x;
    const int lane = tid & 31;
    const int wid = tid >> 5;
    const int wm = wid & 3;
    const int wn = wid >> 2;
    const int m0 = (bid >> 2) * 128;
    const int hh = bid & 3;
    const int n0 = hh * 128;

    float acc[2][8][4];
#pragma unroll
    for (int f = 0; f < 2; f++)
#pragma unroll
        for (int g = 0; g < 8; g++)
#pragma unroll
            for (int e = 0; e < 4; e++) acc[f][g][e] = 0.f;

    const int lr = lane & 15;
    const int lk = (lane >> 4) * 8;

    for (int k0 = 0; k0 < FF; k0 += 32) {
#pragma unroll
        for (int i = 0; i < 4; i++) {
            int idx = i * 256 + tid;
            int r = idx >> 3, c = idx & 7;
            float4 v = *reinterpret_cast<const float4*>(hp + (size_t)(m0 + r) * FF + k0 + c * 4);
            __half2 lo = __floats2half2_rn(v.x, v.y);
            __half2 hi = __floats2half2_rn(v.z, v.w);
            uint2 u = { *reinterpret_cast<uint32_t*>(&lo), *reinterpret_cast<uint32_t*>(&hi) };
            *reinterpret_cast<uint2*>(sm + r * 80 + c * 8) = u;
        }
#pragma unroll
        for (int i = 0; i < 4; i++) {
            int idx = i * 256 + tid;
            int kk = idx >> 5, n4 = idx & 31;
            float4 v = *reinterpret_cast<const float4*>(W + (size_t)(k0 + kk) * CC + n0 + n4 * 4);
            *reinterpret_cast<__half*>(sm + 10240 + (n4 * 4 + 0) * 80 + kk * 2) = __float2half(v.x);
            *reinterpret_cast<__half*>(sm + 10240 + (n4 * 4 + 1) * 80 + kk * 2) = __float2half(v.y);
            *reinterpret_cast<__half*>(sm + 10240 + (n4 * 4 + 2) * 80 + kk * 2) = __float2half(v.z);
            *reinterpret_cast<__half*>(sm + 10240 + (n4 * 4 + 3) * 80 + kk * 2) = __float2half(v.w);
        }
        __syncthreads();
#pragma unroll
        for (int kk = 0; kk < 2; kk++) {
            const uint32_t koff = (kk * 16 + lk) * 2;
            uint32_t af[2][4], bf[4][4];
#pragma unroll
            for (int f = 0; f < 2; f++)
                ldsm4(af[f][0], af[f][1], af[f][2], af[f][3],
                      sb + (wm * 32 + f * 16 + lr) * 80 + koff);
#pragma unroll
            for (int g = 0; g < 4; g++)
                ldsm4(bf[g][0], bf[g][1], bf[g][2], bf[g][3],
                      sb + 10240 + (wn * 64 + g * 16 + lr) * 80 + koff);
#pragma unroll
            for (int f = 0; f < 2; f++)
#pragma unroll
                for (int g = 0; g < 4; g++) {
                    mma16816(acc[f][g * 2 + 0], af[f], bf[g][0], bf[g][2]);
                    mma16816(acc[f][g * 2 + 1], af[f], bf[g][1], bf[g][3]);
                }
        }
        __syncthreads();
    }

#pragma unroll
    for (int f = 0; f < 2; f++)
#pragma unroll
        for (int g = 0; g < 8; g++)
#pragma unroll
            for (int e = 0; e < 4; e++) {
                float x = acc[f][g][e];
                acc[f][g][e] = (x >= 0.f) ? x : 0.1f * x;
            }

    float av0[8], av1[8];
#pragma unroll
    for (int g = 0; g < 8; g++) {
        int col = wn * 64 + g * 8 + (lane & 3) * 2;
        av0[g] = av[hh * 256 + 128 + col];
        av1[g] = av[hh * 256 + 128 + col + 1];
    }
#pragma unroll
    for (int f = 0; f < 2; f++) {
        float s0 = 0.f, s1 = 0.f;
#pragma unroll
        for (int g = 0; g < 8; g++) {
            s0 += acc[f][g][0] * av0[g] + acc[f][g][1] * av1[g];
            s1 += acc[f][g][2] * av0[g] + acc[f][g][3] * av1[g];
        }
        s0 += __shfl_xor_sync(0xFFFFFFFFu, s0, 1);
        s0 += __shfl_xor_sync(0xFFFFFFFFu, s0, 2);
        s1 += __shfl_xor_sync(0xFFFFFFFFu, s1, 1);
        s1 += __shfl_xor_sync(0xFFFFFFFFu, s1, 2);
        if ((lane & 3) == 0) {
            int row = wm * 32 + f * 16 + (lane >> 2);
            tgtp[wn * 128 + row] = s0;
            tgtp[wn * 128 + row + 8] = s1;
        }
    }

#pragma unroll
    for (int f = 0; f < 2; f++) {
        int row = wm * 32 + f * 16 + (lane >> 2);
#pragma unroll
        for (int g = 0; g < 8; g++) {
            int c0 = wn * 64 + g * 8 + (lane & 3) * 2;
            *reinterpret_cast<__half*>(sm + c0 * 272 + row * 2)       = __float2half(acc[f][g][0]);
            *reinterpret_cast<__half*>(sm + (c0 + 1) * 272 + row * 2) = __float2half(acc[f][g][1]);
            *reinterpret_cast<__half*>(sm + c0 * 272 + (row + 8) * 2)       = __float2half(acc[f][g][2]);
            *reinterpret_cast<__half*>(sm + (c0 + 1) * 272 + (row + 8) * 2) = __float2half(acc[f][g][3]);
        }
    }
    __syncthreads();

    if (tid < 128)
        g_tgt[hh * NN + m0 + tid] = tgtp[tid] + tgtp[128 + tid];

#pragma unroll
    for (int i = 0; i < 8; i++) {
        int idx = i * 256 + tid;
        int c = idx >> 4, q = idx & 15;
        *reinterpret_cast<uint4*>(g_htT + (size_t)(hh * 128 + c) * NN + m0 + q * 8) =
            *reinterpret_cast<uint4*>(sm + c * 272 + q * 16);
    }
}

// ---------------------------------------------------------------------------
// Kernel maxw: per-head max + w = exp(tgt - max)
// ---------------------------------------------------------------------------
__global__ __launch_bounds__(256) void k_maxw() {
    __shared__ float red[256];
    const int hh = blockIdx.x;
    const int tid = threadIdx.x;
    float m = -1e30f;
    for (int j = tid; j < NN; j += 256) m = fmaxf(m, g_tgt[hh * NN + j]);
    red[tid] = m;
    __syncthreads();
#pragma unroll
    for (int s = 128; s; s >>= 1) {
        if (tid < s) red[tid] = fmaxf(red[tid], red[tid + s]);
        __syncthreads();
    }
    const float mh = red[0];
    for (int j = tid; j < NN; j += 256)
        g_wT[hh * NN + j] = __float2half(expf(g_tgt[hh * NN + j] - mh));
}

// ---------------------------------------------------------------------------
// Kernel buildVT: VT[n][j] = htT[n][j] * wT[n>>7][j]
// ---------------------------------------------------------------------------
__global__ __launch_bounds__(256) void k_buildVT() {
    size_t idx = ((size_t)blockIdx.x * 256 + threadIdx.x) * 8;
    int n = (int)(idx >> 13);
    int j = (int)(idx & 8191);
    uint4 hv = *reinterpret_cast<const uint4*>(g_htT + idx);
    const __half2* wp = reinterpret_cast<const __half2*>(g_wT + (size_t)(n >> 7) * NN + j);
    __half2* hp2 = reinterpret_cast<__half2*>(&hv);
#pragma unroll
    for (int e = 0; e < 4; e++) hp2[e] = __hmul2(hp2[e], wp[e]);
    *reinterpret_cast<uint4*>(g_VT + idx) = hv;
}

// ---------------------------------------------------------------------------
// Kernel aggr: O += A[:, kbase:kbase+4096] @ V[kbase:...]  (r8 mainloop)
// CTA 256x128, 8 warps, warp 64x64, KST 64, NST 4, single sync/stage.
// grid (4 n fast, 32 m) = 128 CTAs. den fused on n-tile 0, wn==0.
// ---------------------------------------------------------------------------
__device__ __forceinline__ void load_stage(int t, uint32_t sb, int m0, int n0,
                                           int kbase, int tid) {
    const int k0 = kbase + t * KST;
    const uint32_t base = sb + (t & (NST - 1)) * STAGE;
#pragma unroll
    for (int i = 0; i < 8; i++) {
        int idx = i * 256 + tid;
        int r = idx >> 3, c = idx & 7;
        cp16(base + swz(r, c), g_Ah + (size_t)(m0 + r) * NN + k0 + c * 8);
    }
#pragma unroll
    for (int i = 0; i < 4; i++) {
        int idx = i * 256 + tid;
        int r = idx >> 3, c = idx & 7;
        cp16(base + A_BYTES + swz(r, c), g_VT + (size_t)(n0 + r) * NN + k0 + c * 8);
    }
    if (tid < 128) {
        int r = tid >> 3, c = tid & 7;
        cp16(base + A_BYTES + B_BYTES + swz(r, c), g_wT + (size_t)r * NN + k0 + c * 8);
    }
}

__global__ __launch_bounds__(256, 1) void k_aggr_mma(int kbase, int accum) {
    extern __shared__ __align__(128) char smem[];
    const uint32_t sb = smem_u32(smem);
    const int tid = threadIdx.x;
    const int lane = tid & 31;
    const int wid = tid >> 5;
    const int wm = wid & 3;
    const int wn = wid >> 2;
    const int n0 = blockIdx.x * 128;
    const int m0 = blockIdx.y * 256;
    const bool do_den = (blockIdx.x == 0) && (wn == 0);

    float acc[4][8][4];
#pragma unroll
    for (int f = 0; f < 4; f++)
#pragma unroll
        for (int g = 0; g < 8; g++)
#pragma unroll
            for (int e = 0; e < 4; e++) acc[f][g][e] = 0.f;
    float dacc[4][4];
#pragma unroll
    for (int f = 0; f < 4; f++)
#pragma unroll
        for (int e = 0; e < 4; e++) dacc[f][e] = 0.f;

#pragma unroll
    for (int s = 0; s < NST - 1; s++) {
        load_stage(s, sb, m0, n0, kbase, tid);
        cp_commit();
    }

    const int lr = lane & 15;
    const int lcol = lane >> 4;

    const int S = KHALF / KST;  // 64
    for (int s = 0; s < S; s++) {
        asm volatile("cp.async.wait_group %0;" :: "n"(NST - 2) : "memory");
        __syncthreads();
        const uint32_t st = sb + (s & (NST - 1)) * STAGE;
#pragma unroll
        for (int kk = 0; kk < 4; kk++) {
            const int c16 = kk * 2 + lcol;
            uint32_t af[4][4], bf[4][4];
#pragma unroll
            for (int f = 0; f < 4; f++) {
                int r = wm * 64 + f * 16 + lr;
                ldsm4(af[f][0], af[f][1], af[f][2], af[f][3], st + swz(r, c16));
            }
#pragma unroll
            for (int g = 0; g < 4; g++) {
                int r = wn * 64 + g * 16 + lr;
                ldsm4(bf[g][0], bf[g][1], bf[g][2], bf[g][3],
                      st + A_BYTES + swz(r, c16));
            }
#pragma unroll
            for (int f = 0; f < 4; f++)
#pragma unroll
                for (int g = 0; g < 4; g++) {
                    mma16816(acc[f][g * 2 + 0], af[f], bf[g][0], bf[g][2]);
                    mma16816(acc[f][g * 2 + 1], af[f], bf[g][1], bf[g][3]);
                }
            if (do_den) {
                uint32_t bw[4];
                ldsm4(bw[0], bw[1], bw[2], bw[3],
                      st + A_BYTES + B_BYTES + swz(lr, c16));
#pragma unroll
                for (int f = 0; f < 4; f++)
                    mma16816(dacc[f], af[f], bw[0], bw[2]);
            }
        }
        const int t2 = s + NST - 1;
        if (t2 < S) load_stage(t2, sb, m0, n0, kbase, tid);
        cp_commit();
    }

    // epilogue: numerators (write or accumulate)
#pragma unroll
    for (int f = 0; f < 4; f++) {
        const int row = m0 + wm * 64 + f * 16 + (lane >> 2);
#pragma unroll
        for (int g = 0; g < 8; g++) {
            const int col = n0 + wn * 64 + g * 8 + (lane & 3) * 2;
            float* p0 = g_O + (size_t)row * CC + col;
            float* p1 = g_O + (size_t)(row + 8) * CC + col;
            float2 v0 = {acc[f][g][0], acc[f][g][1]};
            float2 v1 = {acc[f][g][2], acc[f][g][3]};
            if (accum) {
                float2 o0 = *reinterpret_cast<float2*>(p0);
                float2 o1 = *reinterpret_cast<float2*>(p1);
                v0.x += o0.x; v0.y += o0.y;
                v1.x += o1.x; v1.y += o1.y;
            }
            *reinterpret_cast<float2*>(p0) = v0;
            *reinterpret_cast<float2*>(p1) = v1;
        }
    }
    if (do_den) {
        const int c2 = (lane & 3) * 2;
        if (c2 < 4) {
#pragma unroll
            for (int f = 0; f < 4; f++) {
                const int row = m0 + wm * 64 + f * 16 + (lane >> 2);
                if (accum) {
                    g_den[row * 4 + c2 + 0] += dacc[f][0];
                    g_den[row * 4 + c2 + 1] += dacc[f][1];
                    g_den[(row + 8) * 4 + c2 + 0] += dacc[f][2];
                    g_den[(row + 8) * 4 + c2 + 1] += dacc[f][3];
                } else {
                    g_den[row * 4 + c2 + 0] = dacc[f][0];
                    g_den[row * 4 + c2 + 1] = dacc[f][1];
                    g_den[(row + 8) * 4 + c2 + 0] = dacc[f][2];
                    g_den[(row + 8) * 4 + c2 + 1] = dacc[f][3];
                }
            }
        }
    }
}

// ---------------------------------------------------------------------------
// Kernel out: out[i][d] = 0.25 * sum_h num[h]/den[h]
// ---------------------------------------------------------------------------
__global__ __launch_bounds__(128) void k_out(float* __restrict__ out) {
    const int i = blockIdx.x;
    const int d = threadIdx.x;
    __shared__ float inv[4];
    if (d < 4) inv[d] = 1.0f / g_den[i * 4 + d];
    __syncthreads();
    float s = 0.f;
#pragma unroll
    for (int h = 0; h < 4; h++) s += g_O[(size_t)i * CC + h * DD + d] * inv[h];
    out[(size_t)i * DD + d] = 0.25f * s;
}

// ---------------------------------------------------------------------------
extern "C" void kernel_launch(void* const* d_in, const int* in_sizes, int n_in,
                              void* d_out, int out_size) {
    const float* h   = (const float*)d_in[0];
    const int*   adj = (const int*)d_in[1];
    const float* W   = (const float*)d_in[2];
    const float* a   = (const float*)d_in[3];
    float* out = (float*)d_out;

    static cudaStream_t s1;
    static cudaEvent_t e0, ec0, ec1;
    static int init_done = 0;
    if (!init_done) {
        cudaFuncSetAttribute(k_aggr_mma, cudaFuncAttributeMaxDynamicSharedMemorySize, SMEMB);
        cudaStreamCreateWithFlags(&s1, cudaStreamNonBlocking);
        cudaEventCreateWithFlags(&e0, cudaEventDisableTiming);
        cudaEventCreateWithFlags(&ec0, cudaEventDisableTiming);
        cudaEventCreateWithFlags(&ec1, cudaEventDisableTiming);
        init_done = 1;
    }

    // fork side stream for conversion halves
    cudaEventRecord(e0, 0);
    cudaStreamWaitEvent(s1, e0, 0);
    k_conv<<<16384, 256, 0, s1>>>(adj, 0);          // half 0
    cudaEventRecord(ec0, s1);
    k_conv<<<16384, 256, 0, s1>>>(adj, KHALF);      // half 1 (overlaps aggr phase 0)
    cudaEventRecord(ec1, s1);

    // prep chain on main stream (concurrent with conv half 0)
    k_proj<<<256, 256>>>(h, W, a);
    k_maxw<<<4, 256>>>();
    k_buildVT<<<2048, 256>>>();

    // aggregation phase 0 (needs conv half 0 + VT)
    cudaStreamWaitEvent(0, ec0, 0);
    k_aggr_mma<<<dim3(4, 32), 256, SMEMB>>>(0, 0);
    // aggregation phase 1 (needs conv half 1)
    cudaStreamWaitEvent(0, ec1, 0);
    k_aggr_mma<<<dim3(4, 32), 256, SMEMB>>>(KHALF, 1);

    k_out<<<8192, 128>>>(out);
}

// round 12
// speedup vs baseline: 2.8441x; 1.0555x over previous
#include <cuda_runtime.h>
#include <cuda_fp16.h>
#include <math.h>
#include <stdint.h>

// Problem constants
#define NN 8192
#define FF 256
#define DD 128
#define CC 512          // NH*DD feature columns (GEMM N = 512)

// aggr GEMM tiling (r8 proven): CTA 256x128, 8 warps (4m x 2n), warp 64x64
// XOR-swizzled smem rows (128B), 16B chunk c' = c ^ (r&7)
#define KST 64                    // fp16 K elements per stage
#define NST 4                     // pipeline stages
#define A_BYTES (256 * 128)       // 32768
#define B_BYTES (128 * 128)       // 16384
#define B2_BYTES (16 * 128)       // 2048
#define STAGE (A_BYTES + B_BYTES + B2_BYTES)  // 51200
#define SMEMB (NST * STAGE)       // 204800

// Scratch (device globals; zero-initialized at module load)
__device__ __half g_htT[(size_t)CC * NN];   // 8 MB  lrelu(h@W) transposed [c][j]
__device__ float  g_tgt[4 * NN];
__device__ __half g_wT[16 * NN];            // rows 0..3 = w_h[j]; rows 4..15 zero
__device__ __half g_Ah[(size_t)NN * NN];    // 128 MB adjacency as fp16
__device__ __half g_VT[(size_t)CC * NN];    // 8 MB  V^T = w * htT
__device__ float  g_O[(size_t)NN * CC];     // 16 MB numerators
__device__ float  g_den[NN * 4];            // denominators

// ---------------------------------------------------------------------------
// helpers (sm_80-compatible PTX only)
// ---------------------------------------------------------------------------
__device__ __forceinline__ uint32_t smem_u32(const void* p) {
    uint32_t a;
    asm("{ .reg .u64 t; cvta.to.shared.u64 t, %1; cvt.u32.u64 %0, t; }" : "=r"(a) : "l"(p));
    return a;
}
static __device__ __forceinline__ void cp16(uint32_t dst, const void* src) {
    asm volatile("cp.async.cg.shared.global [%0], [%1], 16;" :: "r"(dst), "l"(src));
}
static __device__ __forceinline__ void cp_commit() {
    asm volatile("cp.async.commit_group;" ::: "memory");
}
__device__ __forceinline__ void ldsm4(uint32_t& r0, uint32_t& r1, uint32_t& r2,
                                      uint32_t& r3, uint32_t addr) {
    asm volatile("ldmatrix.sync.aligned.m8n8.x4.shared.b16 {%0,%1,%2,%3}, [%4];"
                 : "=r"(r0), "=r"(r1), "=r"(r2), "=r"(r3) : "r"(addr));
}
__device__ __forceinline__ void mma16816(float* d, const uint32_t* a,
                                         uint32_t b0, uint32_t b1) {
    asm volatile("mma.sync.aligned.m16n8k16.row.col.f32.f16.f16.f32 "
                 "{%0,%1,%2,%3}, {%4,%5,%6,%7}, {%8,%9}, {%0,%1,%2,%3};"
                 : "+f"(d[0]), "+f"(d[1]), "+f"(d[2]), "+f"(d[3])
                 : "r"(a[0]), "r"(a[1]), "r"(a[2]), "r"(a[3]), "r"(b0), "r"(b1));
}
// swizzled byte offset: row r, 16B chunk c (0..7) within a 128B-row tile
__device__ __forceinline__ uint32_t swz(int r, int c) {
    return (uint32_t)(r * 128 + ((c ^ (r & 7)) << 4));
}

// ---------------------------------------------------------------------------
// Kernel conv: int32 adjacency -> fp16 (full matrix)
// bit trick: (a|b<<16)*0x3C00 packs {0,1}x{0,1} -> fp16x2 exactly
// ---------------------------------------------------------------------------
__global__ __launch_bounds__(256) void k_conv(const int* __restrict__ A) {
    size_t idx = ((size_t)blockIdx.x * 256 + threadIdx.x) * 8;
    int4 a = *reinterpret_cast<const int4*>(A + idx);
    int4 b = *reinterpret_cast<const int4*>(A + idx + 4);
    uint4 o;
    o.x = (uint32_t)(a.x | (a.y << 16)) * 0x3C00u;
    o.y = (uint32_t)(a.z | (a.w << 16)) * 0x3C00u;
    o.z = (uint32_t)(b.x | (b.y << 16)) * 0x3C00u;
    o.w = (uint32_t)(b.z | (b.w << 16)) * 0x3C00u;
    *reinterpret_cast<uint4*>(g_Ah + idx) = o;
}

// ---------------------------------------------------------------------------
// Kernel proj: HMMA fp16 proj + LeakyReLU + tgt dot + transposed fp16 store
// ---------------------------------------------------------------------------
__global__ __launch_bounds__(256) void k_proj(const float* __restrict__ hp,
                                              const float* __restrict__ W,
                                              const float* __restrict__ av) {
    __shared__ __align__(16) char sm[34816 + 1024];
    const int bid = blockIdx.x;
    const uint32_t sb = smem_u32(sm);
    float* tgtp = reinterpret_cast<float*>(sm + 34816);
    const int tid = threadIdx.x;
    const int lane = tid & 31;
    const int wid = tid >> 5;
    const int wm = wid & 3;
    const int wn = wid >> 2;
    const int m0 = (bid >> 2) * 128;
    const int hh = bid & 3;
    const int n0 = hh * 128;

    float acc[2][8][4];
#pragma unroll
    for (int f = 0; f < 2; f++)
#pragma unroll
        for (int g = 0; g < 8; g++)
#pragma unroll
            for (int e = 0; e < 4; e++) acc[f][g][e] = 0.f;

    const int lr = lane & 15;
    const int lk = (lane >> 4) * 8;

    for (int k0 = 0; k0 < FF; k0 += 32) {
#pragma unroll
        for (int i = 0; i < 4; i++) {
            int idx = i * 256 + tid;
            int r = idx >> 3, c = idx & 7;
            float4 v = *reinterpret_cast<const float4*>(hp + (size_t)(m0 + r) * FF + k0 + c * 4);
            __half2 lo = __floats2half2_rn(v.x, v.y);
            __half2 hi = __floats2half2_rn(v.z, v.w);
            uint2 u = { *reinterpret_cast<uint32_t*>(&lo), *reinterpret_cast<uint32_t*>(&hi) };
            *reinterpret_cast<uint2*>(sm + r * 80 + c * 8) = u;
        }
#pragma unroll
        for (int i = 0; i < 4; i++) {
            int idx = i * 256 + tid;
            int kk = idx >> 5, n4 = idx & 31;
            float4 v = *reinterpret_cast<const float4*>(W + (size_t)(k0 + kk) * CC + n0 + n4 * 4);
            *reinterpret_cast<__half*>(sm + 10240 + (n4 * 4 + 0) * 80 + kk * 2) = __float2half(v.x);
            *reinterpret_cast<__half*>(sm + 10240 + (n4 * 4 + 1) * 80 + kk * 2) = __float2half(v.y);
            *reinterpret_cast<__half*>(sm + 10240 + (n4 * 4 + 2) * 80 + kk * 2) = __float2half(v.z);
            *reinterpret_cast<__half*>(sm + 10240 + (n4 * 4 + 3) * 80 + kk * 2) = __float2half(v.w);
        }
        __syncthreads();
#pragma unroll
        for (int kk = 0; kk < 2; kk++) {
            const uint32_t koff = (kk * 16 + lk) * 2;
            uint32_t af[2][4], bf[4][4];
#pragma unroll
            for (int f = 0; f < 2; f++)
                ldsm4(af[f][0], af[f][1], af[f][2], af[f][3],
                      sb + (wm * 32 + f * 16 + lr) * 80 + koff);
#pragma unroll
            for (int g = 0; g < 4; g++)
                ldsm4(bf[g][0], bf[g][1], bf[g][2], bf[g][3],
                      sb + 10240 + (wn * 64 + g * 16 + lr) * 80 + koff);
#pragma unroll
            for (int f = 0; f < 2; f++)
#pragma unroll
                for (int g = 0; g < 4; g++) {
                    mma16816(acc[f][g * 2 + 0], af[f], bf[g][0], bf[g][2]);
                    mma16816(acc[f][g * 2 + 1], af[f], bf[g][1], bf[g][3]);
                }
        }
        __syncthreads();
    }

#pragma unroll
    for (int f = 0; f < 2; f++)
#pragma unroll
        for (int g = 0; g < 8; g++)
#pragma unroll
            for (int e = 0; e < 4; e++) {
                float x = acc[f][g][e];
                acc[f][g][e] = (x >= 0.f) ? x : 0.1f * x;
            }

    float av0[8], av1[8];
#pragma unroll
    for (int g = 0; g < 8; g++) {
        int col = wn * 64 + g * 8 + (lane & 3) * 2;
        av0[g] = av[hh * 256 + 128 + col];
        av1[g] = av[hh * 256 + 128 + col + 1];
    }
#pragma unroll
    for (int f = 0; f < 2; f++) {
        float s0 = 0.f, s1 = 0.f;
#pragma unroll
        for (int g = 0; g < 8; g++) {
            s0 += acc[f][g][0] * av0[g] + acc[f][g][1] * av1[g];
            s1 += acc[f][g][2] * av0[g] + acc[f][g][3] * av1[g];
        }
        s0 += __shfl_xor_sync(0xFFFFFFFFu, s0, 1);
        s0 += __shfl_xor_sync(0xFFFFFFFFu, s0, 2);
        s1 += __shfl_xor_sync(0xFFFFFFFFu, s1, 1);
        s1 += __shfl_xor_sync(0xFFFFFFFFu, s1, 2);
        if ((lane & 3) == 0) {
            int row = wm * 32 + f * 16 + (lane >> 2);
            tgtp[wn * 128 + row] = s0;
            tgtp[wn * 128 + row + 8] = s1;
        }
    }

#pragma unroll
    for (int f = 0; f < 2; f++) {
        int row = wm * 32 + f * 16 + (lane >> 2);
#pragma unroll
        for (int g = 0; g < 8; g++) {
            int c0 = wn * 64 + g * 8 + (lane & 3) * 2;
            *reinterpret_cast<__half*>(sm + c0 * 272 + row * 2)       = __float2half(acc[f][g][0]);
            *reinterpret_cast<__half*>(sm + (c0 + 1) * 272 + row * 2) = __float2half(acc[f][g][1]);
            *reinterpret_cast<__half*>(sm + c0 * 272 + (row + 8) * 2)       = __float2half(acc[f][g][2]);
            *reinterpret_cast<__half*>(sm + (c0 + 1) * 272 + (row + 8) * 2) = __float2half(acc[f][g][3]);
        }
    }
    __syncthreads();

    if (tid < 128)
        g_tgt[hh * NN + m0 + tid] = tgtp[tid] + tgtp[128 + tid];

#pragma unroll
    for (int i = 0; i < 8; i++) {
        int idx = i * 256 + tid;
        int c = idx >> 4, q = idx & 15;
        *reinterpret_cast<uint4*>(g_htT + (size_t)(hh * 128 + c) * NN + m0 + q * 8) =
            *reinterpret_cast<uint4*>(sm + c * 272 + q * 16);
    }
}

// ---------------------------------------------------------------------------
// Kernel maxw: per-head max + w = exp(tgt - max)
// ---------------------------------------------------------------------------
__global__ __launch_bounds__(256) void k_maxw() {
    __shared__ float red[256];
    const int hh = blockIdx.x;
    const int tid = threadIdx.x;
    float m = -1e30f;
    for (int j = tid; j < NN; j += 256) m = fmaxf(m, g_tgt[hh * NN + j]);
    red[tid] = m;
    __syncthreads();
#pragma unroll
    for (int s = 128; s; s >>= 1) {
        if (tid < s) red[tid] = fmaxf(red[tid], red[tid + s]);
        __syncthreads();
    }
    const float mh = red[0];
    for (int j = tid; j < NN; j += 256)
        g_wT[hh * NN + j] = __float2half(expf(g_tgt[hh * NN + j] - mh));
}

// ---------------------------------------------------------------------------
// Kernel buildVT: VT[n][j] = htT[n][j] * wT[n>>7][j]
// ---------------------------------------------------------------------------
__global__ __launch_bounds__(256) void k_buildVT() {
    size_t idx = ((size_t)blockIdx.x * 256 + threadIdx.x) * 8;
    int n = (int)(idx >> 13);
    int j = (int)(idx & 8191);
    uint4 hv = *reinterpret_cast<const uint4*>(g_htT + idx);
    const __half2* wp = reinterpret_cast<const __half2*>(g_wT + (size_t)(n >> 7) * NN + j);
    __half2* hp2 = reinterpret_cast<__half2*>(&hv);
#pragma unroll
    for (int e = 0; e < 4; e++) hp2[e] = __hmul2(hp2[e], wp[e]);
    *reinterpret_cast<uint4*>(g_VT + idx) = hv;
}

// ---------------------------------------------------------------------------
// Kernel aggr: O = A @ V  (r8 mainloop, byte-identical)
// CTA 256x128, 8 warps, warp 64x64, KST 64, NST 4, single sync/stage.
// grid (4 n fast, 32 m) = 128 CTAs (one/SM). den fused on n-tile 0, wn==0.
// ---------------------------------------------------------------------------
__device__ __forceinline__ void load_stage(int t, uint32_t sb, int m0, int n0, int tid) {
    const int k0 = t * KST;
    const uint32_t base = sb + (t & (NST - 1)) * STAGE;
#pragma unroll
    for (int i = 0; i < 8; i++) {
        int idx = i * 256 + tid;
        int r = idx >> 3, c = idx & 7;
        cp16(base + swz(r, c), g_Ah + (size_t)(m0 + r) * NN + k0 + c * 8);
    }
#pragma unroll
    for (int i = 0; i < 4; i++) {
        int idx = i * 256 + tid;
        int r = idx >> 3, c = idx & 7;
        cp16(base + A_BYTES + swz(r, c), g_VT + (size_t)(n0 + r) * NN + k0 + c * 8);
    }
    if (tid < 128) {
        int r = tid >> 3, c = tid & 7;
        cp16(base + A_BYTES + B_BYTES + swz(r, c), g_wT + (size_t)r * NN + k0 + c * 8);
    }
}

__global__ __launch_bounds__(256, 1) void k_aggr_mma() {
    extern __shared__ __align__(128) char smem[];
    const uint32_t sb = smem_u32(smem);
    const int tid = threadIdx.x;
    const int lane = tid & 31;
    const int wid = tid >> 5;
    const int wm = wid & 3;
    const int wn = wid >> 2;
    const int n0 = blockIdx.x * 128;
    const int m0 = blockIdx.y * 256;
    const bool do_den = (blockIdx.x == 0) && (wn == 0);

    float acc[4][8][4];
#pragma unroll
    for (int f = 0; f < 4; f++)
#pragma unroll
        for (int g = 0; g < 8; g++)
#pragma unroll
            for (int e = 0; e < 4; e++) acc[f][g][e] = 0.f;
    float dacc[4][4];
#pragma unroll
    for (int f = 0; f < 4; f++)
#pragma unroll
        for (int e = 0; e < 4; e++) dacc[f][e] = 0.f;

#pragma unroll
    for (int s = 0; s < NST - 1; s++) {
        load_stage(s, sb, m0, n0, tid);
        cp_commit();
    }

    const int lr = lane & 15;
    const int lcol = lane >> 4;

    const int S = NN / KST;  // 128
    for (int s = 0; s < S; s++) {
        asm volatile("cp.async.wait_group %0;" :: "n"(NST - 2) : "memory");
        __syncthreads();
        const uint32_t st = sb + (s & (NST - 1)) * STAGE;
#pragma unroll
        for (int kk = 0; kk < 4; kk++) {
            const int c16 = kk * 2 + lcol;
            uint32_t af[4][4], bf[4][4];
#pragma unroll
            for (int f = 0; f < 4; f++) {
                int r = wm * 64 + f * 16 + lr;
                ldsm4(af[f][0], af[f][1], af[f][2], af[f][3], st + swz(r, c16));
            }
#pragma unroll
            for (int g = 0; g < 4; g++) {
                int r = wn * 64 + g * 16 + lr;
                ldsm4(bf[g][0], bf[g][1], bf[g][2], bf[g][3],
                      st + A_BYTES + swz(r, c16));
            }
#pragma unroll
            for (int f = 0; f < 4; f++)
#pragma unroll
                for (int g = 0; g < 4; g++) {
                    mma16816(acc[f][g * 2 + 0], af[f], bf[g][0], bf[g][2]);
                    mma16816(acc[f][g * 2 + 1], af[f], bf[g][1], bf[g][3]);
                }
            if (do_den) {
                uint32_t bw[4];
                ldsm4(bw[0], bw[1], bw[2], bw[3],
                      st + A_BYTES + B_BYTES + swz(lr, c16));
#pragma unroll
                for (int f = 0; f < 4; f++)
                    mma16816(dacc[f], af[f], bw[0], bw[2]);
            }
        }
        const int t2 = s + NST - 1;
        if (t2 < S) load_stage(t2, sb, m0, n0, tid);
        cp_commit();
    }

    // epilogue: numerators
#pragma unroll
    for (int f = 0; f < 4; f++) {
        const int row = m0 + wm * 64 + f * 16 + (lane >> 2);
#pragma unroll
        for (int g = 0; g < 8; g++) {
            const int col = n0 + wn * 64 + g * 8 + (lane & 3) * 2;
            float2 v0 = {acc[f][g][0], acc[f][g][1]};
            float2 v1 = {acc[f][g][2], acc[f][g][3]};
            *reinterpret_cast<float2*>(g_O + (size_t)row * CC + col) = v0;
            *reinterpret_cast<float2*>(g_O + (size_t)(row + 8) * CC + col) = v1;
        }
    }
    if (do_den) {
        const int c2 = (lane & 3) * 2;
        if (c2 < 4) {
#pragma unroll
            for (int f = 0; f < 4; f++) {
                const int row = m0 + wm * 64 + f * 16 + (lane >> 2);
                g_den[row * 4 + c2 + 0] = dacc[f][0];
                g_den[row * 4 + c2 + 1] = dacc[f][1];
                g_den[(row + 8) * 4 + c2 + 0] = dacc[f][2];
                g_den[(row + 8) * 4 + c2 + 1] = dacc[f][3];
            }
        }
    }
}

// ---------------------------------------------------------------------------
// Kernel out: out[i][d] = 0.25 * sum_h num[h]/den[h]
// ---------------------------------------------------------------------------
__global__ __launch_bounds__(128) void k_out(float* __restrict__ out) {
    const int i = blockIdx.x;
    const int d = threadIdx.x;
    __shared__ float inv[4];
    if (d < 4) inv[d] = 1.0f / g_den[i * 4 + d];
    __syncthreads();
    float s = 0.f;
#pragma unroll
    for (int h = 0; h < 4; h++) s += g_O[(size_t)i * CC + h * DD + d] * inv[h];
    out[(size_t)i * DD + d] = 0.25f * s;
}

// ---------------------------------------------------------------------------
extern "C" void kernel_launch(void* const* d_in, const int* in_sizes, int n_in,
                              void* d_out, int out_size) {
    const float* h   = (const float*)d_in[0];
    const int*   adj = (const int*)d_in[1];
    const float* W   = (const float*)d_in[2];
    const float* a   = (const float*)d_in[3];
    float* out = (float*)d_out;

    static cudaStream_t s1;
    static cudaEvent_t e0, ec;
    static int init_done = 0;
    if (!init_done) {
        cudaFuncSetAttribute(k_aggr_mma, cudaFuncAttributeMaxDynamicSharedMemorySize, SMEMB);
        cudaStreamCreateWithFlags(&s1, cudaStreamNonBlocking);
        cudaEventCreateWithFlags(&e0, cudaEventDisableTiming);
        cudaEventCreateWithFlags(&ec, cudaEventDisableTiming);
        init_done = 1;
    }

    // fork: full conversion on side stream, concurrent with the whole prep chain
    cudaEventRecord(e0, 0);
    cudaStreamWaitEvent(s1, e0, 0);
    k_conv<<<32768, 256, 0, s1>>>(adj);
    cudaEventRecord(ec, s1);

    // prep chain on main stream (hidden under conv)
    k_proj<<<256, 256>>>(h, W, a);
    k_maxw<<<4, 256>>>();
    k_buildVT<<<2048, 256>>>();

    // join, then the proven r8 aggregation
    cudaStreamWaitEvent(0, ec, 0);
    k_aggr_mma<<<dim3(4, 32), 256, SMEMB>>>();
    k_out<<<8192, 128>>>(out);
}